// round 12
// baseline (speedup 1.0000x reference)
#include <cuda_runtime.h>
#include <cuda_bf16.h>
#include <math.h>
#include <float.h>
#include <stdint.h>

// Problem dims
#define BB 32
#define TT 100
#define SS 100
#define EE 512
#define HH 1024
#define LL 10
#define VV 32000
#define MM (BB*TT)        // 3200
#define TP (TT+2)         // 102 (left-pad 2)

typedef __nv_bfloat16 bf16;

// ---------------- scratch (static device memory; no allocation) ----------------
__device__ float g_xpad[(size_t)BB*TP*HH];
__device__ float g_emb[(size_t)MM*EE];
__device__ float g_conved[(size_t)MM*HH];
__device__ float g_comb[(size_t)MM*EE];
__device__ float g_att[(size_t)MM*SS];
__device__ float g_cbias[(size_t)LL*2*HH];

__device__ bf16 g_wt_h[(size_t)LL*2*HH*3*HH], g_wt_l[(size_t)LL*2*HH*3*HH];
__device__ bf16 g_weh_h[(size_t)HH*EE],  g_weh_l[(size_t)HH*EE];
__device__ bf16 g_whe_h[(size_t)EE*HH],  g_whe_l[(size_t)EE*HH];
__device__ bf16 g_wahe_h[(size_t)EE*HH], g_wahe_l[(size_t)EE*HH];
__device__ bf16 g_waeh_h[(size_t)HH*EE], g_waeh_l[(size_t)HH*EE];
__device__ bf16 g_wfc_h[(size_t)VV*EE],  g_wfc_l[(size_t)VV*EE];
__device__ bf16 g_xpad_h[(size_t)BB*TP*HH], g_xpad_l[(size_t)BB*TP*HH];
__device__ bf16 g_emb_h[(size_t)MM*EE],     g_emb_l[(size_t)MM*EE];
__device__ bf16 g_conved_h[(size_t)MM*HH],  g_conved_l[(size_t)MM*HH];
__device__ bf16 g_attenc_h[(size_t)MM*EE],  g_attenc_l[(size_t)MM*EE];
__device__ bf16 g_comb_h[(size_t)MM*EE],    g_comb_l[(size_t)MM*EE];

__device__ __forceinline__ void splitf(float v, bf16& h, bf16& l) {
    bf16 hh = __float2bfloat16(v);
    h = hh;
    l = __float2bfloat16(v - __bfloat162float(hh));
}

// ---------------- prep: ONE kernel for all weight prep ----------------
#define WT_TOTAL ((size_t)LL*2*HH*3*HH)
#define PREP_REST_TOTAL ((size_t)LL*2*HH + 4*(size_t)HH*EE + (size_t)VV*EE)
#define PREP_TOTAL (WT_TOTAL + PREP_REST_TOTAL)

__global__ void k_prep(const float* __restrict__ w, const float* __restrict__ cb,
                       const float* __restrict__ w_eh, const float* __restrict__ w_he,
                       const float* __restrict__ w_ahe, const float* __restrict__ w_aeh,
                       const float* __restrict__ w_fc) {
    size_t idx = (size_t)blockIdx.x * 256 + threadIdx.x;
    if (idx < WT_TOTAL) {
        int h = (int)(idx & (HH-1));
        size_t r = idx >> 10;
        int k = (int)(r % 3);
        size_t ln = r / 3;
        int np = (int)(ln & (2*HH - 1));
        size_t l = ln >> 11;
        int o = (np & 1) ? (HH + (np >> 1)) : (np >> 1);
        float v = w[(l*2*HH + o)*3*HH + (size_t)h*3 + k];
        splitf(v, g_wt_h[idx], g_wt_l[idx]);
        return;
    }
    idx -= WT_TOTAL;
    const size_t NB = (size_t)LL*2*HH;
    const size_t NW = (size_t)HH*EE;
    if (idx < NB) {
        int np = (int)(idx & (2*HH - 1));
        int l = (int)(idx >> 11);
        int o = (np & 1) ? (HH + (np >> 1)) : (np >> 1);
        g_cbias[idx] = cb[(size_t)l*2*HH + o];
        return;
    }
    idx -= NB;
    if (idx < NW) { splitf(w_eh[idx],  g_weh_h[idx],  g_weh_l[idx]);  return; }
    idx -= NW;
    if (idx < NW) { splitf(w_he[idx],  g_whe_h[idx],  g_whe_l[idx]);  return; }
    idx -= NW;
    if (idx < NW) { splitf(w_ahe[idx], g_wahe_h[idx], g_wahe_l[idx]); return; }
    idx -= NW;
    if (idx < NW) { splitf(w_aeh[idx], g_waeh_h[idx], g_waeh_l[idx]); return; }
    idx -= NW;
    if (idx < (size_t)VV*EE) { splitf(w_fc[idx], g_wfc_h[idx], g_wfc_l[idx]); }
}

__global__ void k_embed(const int* __restrict__ target,
                        const float* __restrict__ src_emb,
                        const float* __restrict__ pos_emb) {
    int idx = blockIdx.x * 256 + threadIdx.x;
    if (idx < MM*EE) {
        int m = idx >> 9;
        int e = idx & (EE-1);
        int t = m % TT;
        float v = src_emb[(size_t)target[m]*EE + e] + pos_emb[(size_t)t*EE + e];
        g_emb[idx] = v;
        splitf(v, g_emb_h[idx], g_emb_l[idx]);
        return;
    }
    int j = idx - MM*EE;
    if (j < BB*2*HH) {
        int b = j >> 11;
        int r = (j >> 10) & 1;
        int h = j & (HH-1);
        size_t p = (size_t)(b*TP + r)*HH + h;
        g_xpad[p] = 0.f;
        g_xpad_h[p] = __float2bfloat16(0.f);
        g_xpad_l[p] = __float2bfloat16(0.f);
    }
}

__global__ void k_attcopy(float* __restrict__ dst) {
    int idx = blockIdx.x * 256 + threadIdx.x;
    if (idx < MM*SS) dst[idx] = g_att[idx];
}

// ---------------- fused attention: energy + softmax + att_enc (+split) ----------------
__global__ __launch_bounds__(256) void k_att(const float* __restrict__ encC,
                                             const float* __restrict__ encComb) {
    __shared__ float sE[32][104];
    const int w = threadIdx.x >> 5, lane = threadIdx.x & 31;
    const int mw = blockIdx.x * 32 + w * 4;
    const int b = mw / TT;

    float cr[4][16];
    #pragma unroll
    for (int r = 0; r < 4; r++) {
        const float4* cp = (const float4*)(g_comb + (size_t)(mw + r)*EE + lane*16);
        #pragma unroll
        for (int q = 0; q < 4; q++) {
            float4 v = cp[q];
            cr[r][q*4+0] = v.x; cr[r][q*4+1] = v.y; cr[r][q*4+2] = v.z; cr[r][q*4+3] = v.w;
        }
    }
    const float* ebase = encC + (size_t)b*SS*EE;
    for (int s = 0; s < SS; s++) {
        const float4* ep = (const float4*)(ebase + (size_t)s*EE + lane*16);
        float ev[16];
        #pragma unroll
        for (int q = 0; q < 4; q++) {
            float4 v = ep[q];
            ev[q*4+0] = v.x; ev[q*4+1] = v.y; ev[q*4+2] = v.z; ev[q*4+3] = v.w;
        }
        #pragma unroll
        for (int r = 0; r < 4; r++) {
            float p = 0.f;
            #pragma unroll
            for (int j = 0; j < 16; j++) p += cr[r][j] * ev[j];
            #pragma unroll
            for (int o = 16; o > 0; o >>= 1) p += __shfl_xor_sync(0xffffffffu, p, o);
            if (lane == 0) sE[w*4 + r][s] = p;
        }
    }
    __syncwarp();

    #pragma unroll
    for (int r = 0; r < 4; r++) {
        float v[4];
        #pragma unroll
        for (int q = 0; q < 4; q++) {
            int s = lane + 32*q;
            v[q] = (s < SS) ? sE[w*4 + r][s] : -FLT_MAX;
        }
        float mx = fmaxf(fmaxf(v[0], v[1]), fmaxf(v[2], v[3]));
        #pragma unroll
        for (int o = 16; o > 0; o >>= 1) mx = fmaxf(mx, __shfl_xor_sync(0xffffffffu, mx, o));
        float e[4]; float sm = 0.f;
        #pragma unroll
        for (int q = 0; q < 4; q++) {
            int s = lane + 32*q;
            e[q] = (s < SS) ? expf(v[q] - mx) : 0.f;
            sm += e[q];
        }
        #pragma unroll
        for (int o = 16; o > 0; o >>= 1) sm += __shfl_xor_sync(0xffffffffu, sm, o);
        float inv = 1.f / sm;
        #pragma unroll
        for (int q = 0; q < 4; q++) {
            int s = lane + 32*q;
            if (s < SS) {
                float a = e[q] * inv;
                sE[w*4 + r][s] = a;
                g_att[(size_t)(mw + r)*SS + s] = a;
            }
        }
    }
    __syncwarp();

    float acc[4][16];
    #pragma unroll
    for (int r = 0; r < 4; r++)
        #pragma unroll
        for (int j = 0; j < 16; j++) acc[r][j] = 0.f;
    const float* cbm = encComb + (size_t)b*SS*EE;
    for (int s = 0; s < SS; s++) {
        const float4* ep = (const float4*)(cbm + (size_t)s*EE + lane*16);
        float ev[16];
        #pragma unroll
        for (int q = 0; q < 4; q++) {
            float4 v = ep[q];
            ev[q*4+0] = v.x; ev[q*4+1] = v.y; ev[q*4+2] = v.z; ev[q*4+3] = v.w;
        }
        #pragma unroll
        for (int r = 0; r < 4; r++) {
            float a = sE[w*4 + r][s];
            #pragma unroll
            for (int j = 0; j < 16; j++) acc[r][j] += a * ev[j];
        }
    }
    #pragma unroll
    for (int r = 0; r < 4; r++) {
        size_t o = (size_t)(mw + r)*EE + lane*16;
        #pragma unroll
        for (int j = 0; j < 16; j++) splitf(acc[r][j], g_attenc_h[o+j], g_attenc_l[o+j]);
    }
}

// ---------------- tensor-core GEMM (bf16x3, 64x128 tile, SW64, 3-stage, 1 barrier/stage) ----------------
#define TMQ 64
#define TNQ 128
#define KT 32
#define A_H_OFF 0
#define A_L_OFF 4096
#define B_H_OFF 8192
#define B_L_OFF 16384
#define STAGE 24576
#define NSTG 3
#define DYN_BYTES (NSTG*STAGE + 128)

__device__ __forceinline__ uint32_t swz64(uint32_t x) { return x ^ ((x >> 3) & 0x30); }

__device__ __forceinline__ void ldsm4(uint32_t r[4], unsigned addr) {
    asm volatile("ldmatrix.sync.aligned.m8n8.x4.shared.b16 {%0,%1,%2,%3}, [%4];\n"
        : "=r"(r[0]), "=r"(r[1]), "=r"(r[2]), "=r"(r[3]) : "r"(addr));
}
__device__ __forceinline__ void mma16816(float c[4], const uint32_t a[4],
                                         uint32_t b0, uint32_t b1) {
    asm volatile(
        "mma.sync.aligned.m16n8k16.row.col.f32.bf16.bf16.f32 "
        "{%0,%1,%2,%3},{%4,%5,%6,%7},{%8,%9},{%0,%1,%2,%3};\n"
        : "+f"(c[0]), "+f"(c[1]), "+f"(c[2]), "+f"(c[3])
        : "r"(a[0]), "r"(a[1]), "r"(a[2]), "r"(a[3]), "r"(b0), "r"(b1));
}
__device__ __forceinline__ void cpasync16(uint32_t dst, const void* src) {
    asm volatile("cp.async.cg.shared.global [%0], [%1], 16;" :: "r"(dst), "l"(src) : "memory");
}
__device__ __forceinline__ void cp_commit() {
    asm volatile("cp.async.commit_group;" ::: "memory");
}
template<int N> __device__ __forceinline__ void cp_wait() {
    asm volatile("cp.async.wait_group %0;" :: "n"(N) : "memory");
}

__global__ __launch_bounds__(256, 3) void gemm_tc(
    const bf16* __restrict__ Ah, const bf16* __restrict__ Al, int amode, int lda,
    const bf16* __restrict__ Wh, const bf16* __restrict__ Wl,
    const float* __restrict__ bias, const float* __restrict__ add, int ldadd,
    float scale, float* __restrict__ C, bf16* __restrict__ Ch, bf16* __restrict__ Cl,
    int cmode, int ldc, int K, int emode,
    float* __restrict__ X, bf16* __restrict__ Xh, bf16* __restrict__ Xl)
{
    extern __shared__ char dynsm[];
    const int tid = threadIdx.x;
    const int lane = tid & 31, warp = tid >> 5;
    const int m0 = blockIdx.y * TMQ, n0 = blockIdx.x * TNQ;
    const unsigned sbase = ((unsigned)__cvta_generic_to_shared(dynsm) + 127u) & ~127u;

    // ---- load maps ----
    size_t a_go; uint32_t a_sd;
    {
        int row = tid >> 2, c = tid & 3;
        int m = m0 + row, rm = m;
        if (amode) { int b = m / TT, t = m - b*TT; rm = b*TP + t + ((amode == 1) ? 2 : 0); }
        a_go = (size_t)rm * lda + c * 8;
        a_sd = swz64((uint32_t)(row * 64 + c * 16));
    }
    size_t w_go[2]; uint32_t b_sd[2];
    #pragma unroll
    for (int i = 0; i < 2; i++) {
        int idx = tid + i * 256;
        int row = idx >> 2, c = idx & 3;
        w_go[i] = (size_t)(n0 + row) * K + c * 8;
        b_sd[i] = swz64((uint32_t)(row * 64 + c * 16));
    }

    const int wm = warp & 1;
    const int wn = warp >> 1;

    // lane-invariant fragment smem offsets (unswizzled linear parts)
    uint32_t a_lin[2], b_lin[2];
    #pragma unroll
    for (int tm = 0; tm < 2; tm++)
        a_lin[tm] = (uint32_t)((wm*32 + tm*16 + (lane & 15)) * 64 + (lane >> 4) * 16);
    #pragma unroll
    for (int tb = 0; tb < 2; tb++)
        b_lin[tb] = (uint32_t)((wn*32 + tb*16 + (lane & 7) + ((lane >> 4) << 3)) * 64
                               + (((lane >> 3) & 1) << 4));

    float acc[2][4][4];
    #pragma unroll
    for (int i = 0; i < 2; i++)
        #pragma unroll
        for (int j = 0; j < 4; j++)
            #pragma unroll
            for (int q = 0; q < 4; q++) acc[i][j][q] = 0.f;

    const int nK = K / KT;

    #define ISSUE_STAGE(s) do {                                               \
        const size_t k0_ = (size_t)(s) * KT;                                  \
        const unsigned stg_ = sbase + (unsigned)(((s) % NSTG) * STAGE);       \
        cpasync16(stg_ + A_H_OFF + a_sd, Ah + a_go + k0_);                    \
        cpasync16(stg_ + A_L_OFF + a_sd, Al + a_go + k0_);                    \
        _Pragma("unroll")                                                     \
        for (int i_ = 0; i_ < 2; i_++) {                                      \
            cpasync16(stg_ + B_H_OFF + b_sd[i_], Wh + w_go[i_] + k0_);        \
            cpasync16(stg_ + B_L_OFF + b_sd[i_], Wl + w_go[i_] + k0_);        \
        }                                                                     \
        cp_commit();                                                          \
    } while (0)

    ISSUE_STAGE(0); ISSUE_STAGE(1);
    for (int s = 0; s < nK; s++) {
        if (s == nK - 1) cp_wait<0>(); else cp_wait<1>();
        __syncthreads();          // stage s published; all consumers of s-1 done
        if (s + 2 < nK) ISSUE_STAGE(s + 2);

        const unsigned bufb = sbase + (unsigned)((s % NSTG) * STAGE);
        #pragma unroll
        for (int kk = 0; kk < 2; kk++) {
            const unsigned kof = kk * 32;
            uint32_t ah[2][4], al[2][4], bh[2][4], bl[2][4];
            #pragma unroll
            for (int tm = 0; tm < 2; tm++) {
                ldsm4(ah[tm], bufb + A_H_OFF + swz64(a_lin[tm] + kof));
                ldsm4(al[tm], bufb + A_L_OFF + swz64(a_lin[tm] + kof));
            }
            #pragma unroll
            for (int tb = 0; tb < 2; tb++) {
                ldsm4(bh[tb], bufb + B_H_OFF + swz64(b_lin[tb] + kof));
                ldsm4(bl[tb], bufb + B_L_OFF + swz64(b_lin[tb] + kof));
            }
            // hi*hi
            #pragma unroll
            for (int tm = 0; tm < 2; tm++)
                #pragma unroll
                for (int j = 0; j < 4; j++)
                    mma16816(acc[tm][j], ah[tm], bh[j>>1][(j&1)*2], bh[j>>1][(j&1)*2+1]);
            // lo*hi
            #pragma unroll
            for (int tm = 0; tm < 2; tm++)
                #pragma unroll
                for (int j = 0; j < 4; j++)
                    mma16816(acc[tm][j], al[tm], bh[j>>1][(j&1)*2], bh[j>>1][(j&1)*2+1]);
            // hi*lo
            #pragma unroll
            for (int tm = 0; tm < 2; tm++)
                #pragma unroll
                for (int j = 0; j < 4; j++)
                    mma16816(acc[tm][j], ah[tm], bl[j>>1][(j&1)*2], bl[j>>1][(j&1)*2+1]);
        }
    }
    #undef ISSUE_STAGE

    // ---------------- epilogue ----------------
    #pragma unroll
    for (int tm = 0; tm < 2; tm++) {
        #pragma unroll
        for (int half = 0; half < 2; half++) {
            int m = m0 + wm*32 + tm*16 + (lane >> 2) + half*8;
            int rm = m;
            if (cmode == 1) { int b = m / TT, t = m - b*TT; rm = b*TP + t + 2; }
            int rmp = 0;
            if (emode == 2) { int b = m / TT, t = m - b*TT; rmp = b*TP + t + 2; }
            size_t crow = (size_t)rm * ldc;
            size_t arow = (size_t)m * ldadd;
            #pragma unroll
            for (int j = 0; j < 4; j++) {
                int n = n0 + wn*32 + j*8 + (lane & 3)*2;
                float v0 = acc[tm][j][half*2 + 0];
                float v1 = acc[tm][j][half*2 + 1];
                if (bias) { v0 += bias[n]; v1 += bias[n+1]; }
                if (emode == 1) {
                    float g = v0 / (1.f + expf(-v1));
                    int h = n >> 1;
                    C[crow + h] = g;
                    splitf(g, Ch[crow + h], Cl[crow + h]);
                } else {
                    if (add) { v0 += add[arow + n]; v1 += add[arow + n + 1]; }
                    v0 *= scale; v1 *= scale;
                    float2 r; r.x = v0; r.y = v1;
                    *(float2*)(C + crow + n) = r;
                    if (Ch) {
                        __nv_bfloat162 hv, lv;
                        splitf(v0, hv.x, lv.x);
                        splitf(v1, hv.y, lv.y);
                        *(__nv_bfloat162*)(Ch + crow + n) = hv;
                        *(__nv_bfloat162*)(Cl + crow + n) = lv;
                    }
                    if (emode == 2) {
                        size_t xrow = (size_t)rmp * ldc;
                        float x0 = (v0 + X[xrow + n]) * scale;
                        float x1 = (v1 + X[xrow + n + 1]) * scale;
                        float2 xr; xr.x = x0; xr.y = x1;
                        *(float2*)(X + xrow + n) = xr;
                        __nv_bfloat162 hv, lv;
                        splitf(x0, hv.x, lv.x);
                        splitf(x1, hv.y, lv.y);
                        *(__nv_bfloat162*)(Xh + xrow + n) = hv;
                        *(__nv_bfloat162*)(Xl + xrow + n) = lv;
                    }
                }
            }
        }
    }
}

static void launch_tc(const bf16* Ah, const bf16* Al, int amode, int lda,
                      const bf16* Wh, const bf16* Wl,
                      const float* bias, const float* add, int ldadd, float scale,
                      float* C, bf16* Ch, bf16* Cl, int cmode, int ldc,
                      int M, int N, int K, int emode = 0,
                      float* X = nullptr, bf16* Xh = nullptr, bf16* Xl = nullptr) {
    dim3 g(N / TNQ, M / TMQ);
    gemm_tc<<<g, 256, DYN_BYTES>>>(Ah, Al, amode, lda, Wh, Wl, bias, add, ldadd,
                                   scale, C, Ch, Cl, cmode, ldc, K, emode, X, Xh, Xl);
}

// ---------------- launch ----------------
extern "C" void kernel_launch(void* const* d_in, const int* in_sizes, int n_in,
                              void* d_out, int out_size) {
    const int*   target   = (const int*)  d_in[0];
    const float* encC     = (const float*)d_in[1];
    const float* encComb  = (const float*)d_in[2];
    const float* src_emb  = (const float*)d_in[3];
    const float* pos_emb  = (const float*)d_in[4];
    const float* w_eh     = (const float*)d_in[5];
    const float* b_eh     = (const float*)d_in[6];
    const float* w_he     = (const float*)d_in[7];
    const float* b_he     = (const float*)d_in[8];
    const float* w_ahe    = (const float*)d_in[9];
    const float* b_ahe    = (const float*)d_in[10];
    const float* w_aeh    = (const float*)d_in[11];
    const float* b_aeh    = (const float*)d_in[12];
    const float* w_fc     = (const float*)d_in[13];
    const float* b_fc     = (const float*)d_in[14];
    const float* conv_w   = (const float*)d_in[15];
    const float* conv_b   = (const float*)d_in[16];
    float* out = (float*)d_out;

    cudaFuncSetAttribute(gemm_tc, cudaFuncAttributeMaxDynamicSharedMemorySize, DYN_BYTES);

    float *p_xpad, *p_emb, *p_conved, *p_comb, *p_cbias;
    bf16 *p_wt_h, *p_wt_l, *p_weh_h, *p_weh_l, *p_whe_h, *p_whe_l;
    bf16 *p_wahe_h, *p_wahe_l, *p_waeh_h, *p_waeh_l, *p_wfc_h, *p_wfc_l;
    bf16 *p_xpad_h, *p_xpad_l, *p_emb_h, *p_emb_l, *p_conved_h, *p_conved_l;
    bf16 *p_attenc_h, *p_attenc_l, *p_comb_h, *p_comb_l;
    cudaGetSymbolAddress((void**)&p_xpad, g_xpad);
    cudaGetSymbolAddress((void**)&p_emb, g_emb);
    cudaGetSymbolAddress((void**)&p_conved, g_conved);
    cudaGetSymbolAddress((void**)&p_comb, g_comb);
    cudaGetSymbolAddress((void**)&p_cbias, g_cbias);
    cudaGetSymbolAddress((void**)&p_wt_h, g_wt_h);   cudaGetSymbolAddress((void**)&p_wt_l, g_wt_l);
    cudaGetSymbolAddress((void**)&p_weh_h, g_weh_h); cudaGetSymbolAddress((void**)&p_weh_l, g_weh_l);
    cudaGetSymbolAddress((void**)&p_whe_h, g_whe_h); cudaGetSymbolAddress((void**)&p_whe_l, g_whe_l);
    cudaGetSymbolAddress((void**)&p_wahe_h, g_wahe_h); cudaGetSymbolAddress((void**)&p_wahe_l, g_wahe_l);
    cudaGetSymbolAddress((void**)&p_waeh_h, g_waeh_h); cudaGetSymbolAddress((void**)&p_waeh_l, g_waeh_l);
    cudaGetSymbolAddress((void**)&p_wfc_h, g_wfc_h); cudaGetSymbolAddress((void**)&p_wfc_l, g_wfc_l);
    cudaGetSymbolAddress((void**)&p_xpad_h, g_xpad_h); cudaGetSymbolAddress((void**)&p_xpad_l, g_xpad_l);
    cudaGetSymbolAddress((void**)&p_emb_h, g_emb_h); cudaGetSymbolAddress((void**)&p_emb_l, g_emb_l);
    cudaGetSymbolAddress((void**)&p_conved_h, g_conved_h); cudaGetSymbolAddress((void**)&p_conved_l, g_conved_l);
    cudaGetSymbolAddress((void**)&p_attenc_h, g_attenc_h); cudaGetSymbolAddress((void**)&p_attenc_l, g_attenc_l);
    cudaGetSymbolAddress((void**)&p_comb_h, g_comb_h); cudaGetSymbolAddress((void**)&p_comb_l, g_comb_l);

    const float SC = 0.7071067811865476f;

    k_prep<<<(unsigned)((PREP_TOTAL + 255) / 256), 256>>>(
        conv_w, conv_b, w_eh, w_he, w_ahe, w_aeh, w_fc);
    k_embed<<<(MM*EE + BB*2*HH + 255) / 256, 256>>>(target, src_emb, pos_emb);

    launch_tc(p_emb_h, p_emb_l, 0, EE, p_weh_h, p_weh_l, b_eh, nullptr, 0, 1.f,
              p_xpad, p_xpad_h, p_xpad_l, 1, HH, MM, HH, EE);

    for (int l = 0; l < LL; l++) {
        const size_t wo = (size_t)l*2*HH*3*HH;
        launch_tc(p_xpad_h, p_xpad_l, 2, HH, p_wt_h + wo, p_wt_l + wo,
                  p_cbias + (size_t)l*2*HH, nullptr, 0, 1.f,
                  p_conved, p_conved_h, p_conved_l, 0, HH, MM, 2*HH, 3*HH, 1);
        launch_tc(p_conved_h, p_conved_l, 0, HH, p_wahe_h, p_wahe_l,
                  b_ahe, p_emb, EE, SC, p_comb, nullptr, nullptr, 0, EE, MM, EE, HH);
        k_att<<<MM/32, 256>>>(encC, encComb);
        launch_tc(p_attenc_h, p_attenc_l, 0, EE, p_waeh_h, p_waeh_l,
                  b_aeh, p_conved, HH, SC, p_conved, p_conved_h, p_conved_l,
                  0, HH, MM, HH, EE, 2, p_xpad, p_xpad_h, p_xpad_l);
    }

    launch_tc(p_xpad_h, p_xpad_l, 1, HH, p_whe_h, p_whe_l, b_he, nullptr, 0, 1.f,
              p_comb, p_comb_h, p_comb_l, 0, EE, MM, EE, HH);
    launch_tc(p_comb_h, p_comb_l, 0, EE, p_wfc_h, p_wfc_l, b_fc, nullptr, 0, 1.f,
              out, nullptr, nullptr, 0, VV, MM, VV, EE);

    const long long ATT_OFF = (long long)MM * VV;
    if ((long long)out_size >= ATT_OFF + (long long)MM*SS) {
        k_attcopy<<<(MM*SS + 255) / 256, 256>>>(out + ATT_OFF);
    }
}

// round 14
// speedup vs baseline: 1.0572x; 1.0572x over previous
#include <cuda_runtime.h>
#include <cuda_bf16.h>
#include <math.h>
#include <float.h>
#include <stdint.h>

// Problem dims
#define BB 32
#define TT 100
#define SS 100
#define EE 512
#define HH 1024
#define LL 10
#define VV 32000
#define MM (BB*TT)        // 3200
#define TP (TT+2)         // 102 (left-pad 2)

typedef __nv_bfloat16 bf16;

// ---------------- scratch (static device memory; no allocation) ----------------
__device__ float g_xpad[(size_t)BB*TP*HH];
__device__ float g_emb[(size_t)MM*EE];
__device__ float g_conved[(size_t)MM*HH];
__device__ float g_comb[(size_t)MM*EE];
__device__ float g_att[(size_t)MM*SS];
__device__ float g_cbias[(size_t)LL*2*HH];

__device__ bf16 g_wt_h[(size_t)LL*2*HH*3*HH], g_wt_l[(size_t)LL*2*HH*3*HH];
__device__ bf16 g_weh_h[(size_t)HH*EE],  g_weh_l[(size_t)HH*EE];
__device__ bf16 g_whe_h[(size_t)EE*HH],  g_whe_l[(size_t)EE*HH];
__device__ bf16 g_wahe_h[(size_t)EE*HH], g_wahe_l[(size_t)EE*HH];
__device__ bf16 g_waeh_h[(size_t)HH*EE], g_waeh_l[(size_t)HH*EE];
__device__ bf16 g_wfc_h[(size_t)VV*EE],  g_wfc_l[(size_t)VV*EE];
__device__ bf16 g_xpad_h[(size_t)BB*TP*HH], g_xpad_l[(size_t)BB*TP*HH];
__device__ bf16 g_emb_h[(size_t)MM*EE],     g_emb_l[(size_t)MM*EE];
__device__ bf16 g_conved_h[(size_t)MM*HH],  g_conved_l[(size_t)MM*HH];
__device__ bf16 g_attenc_h[(size_t)MM*EE],  g_attenc_l[(size_t)MM*EE];
__device__ bf16 g_comb_h[(size_t)MM*EE],    g_comb_l[(size_t)MM*EE];

__device__ __forceinline__ void splitf(float v, bf16& h, bf16& l) {
    bf16 hh = __float2bfloat16(v);
    h = hh;
    l = __float2bfloat16(v - __bfloat162float(hh));
}

// ---------------- prep: ONE kernel for all weight prep ----------------
#define WT_TOTAL ((size_t)LL*2*HH*3*HH)
#define PREP_REST_TOTAL ((size_t)LL*2*HH + 4*(size_t)HH*EE + (size_t)VV*EE)
#define PREP_TOTAL (WT_TOTAL + PREP_REST_TOTAL)

__global__ void k_prep(const float* __restrict__ w, const float* __restrict__ cb,
                       const float* __restrict__ w_eh, const float* __restrict__ w_he,
                       const float* __restrict__ w_ahe, const float* __restrict__ w_aeh,
                       const float* __restrict__ w_fc) {
    size_t idx = (size_t)blockIdx.x * 256 + threadIdx.x;
    if (idx < WT_TOTAL) {
        int h = (int)(idx & (HH-1));
        size_t r = idx >> 10;
        int k = (int)(r % 3);
        size_t ln = r / 3;
        int np = (int)(ln & (2*HH - 1));
        size_t l = ln >> 11;
        int o = (np & 1) ? (HH + (np >> 1)) : (np >> 1);
        float v = w[(l*2*HH + o)*3*HH + (size_t)h*3 + k];
        splitf(v, g_wt_h[idx], g_wt_l[idx]);
        return;
    }
    idx -= WT_TOTAL;
    const size_t NB = (size_t)LL*2*HH;
    const size_t NW = (size_t)HH*EE;
    if (idx < NB) {
        int np = (int)(idx & (2*HH - 1));
        int l = (int)(idx >> 11);
        int o = (np & 1) ? (HH + (np >> 1)) : (np >> 1);
        g_cbias[idx] = cb[(size_t)l*2*HH + o];
        return;
    }
    idx -= NB;
    if (idx < NW) { splitf(w_eh[idx],  g_weh_h[idx],  g_weh_l[idx]);  return; }
    idx -= NW;
    if (idx < NW) { splitf(w_he[idx],  g_whe_h[idx],  g_whe_l[idx]);  return; }
    idx -= NW;
    if (idx < NW) { splitf(w_ahe[idx], g_wahe_h[idx], g_wahe_l[idx]); return; }
    idx -= NW;
    if (idx < NW) { splitf(w_aeh[idx], g_waeh_h[idx], g_waeh_l[idx]); return; }
    idx -= NW;
    if (idx < (size_t)VV*EE) { splitf(w_fc[idx], g_wfc_h[idx], g_wfc_l[idx]); }
}

__global__ void k_embed(const int* __restrict__ target,
                        const float* __restrict__ src_emb,
                        const float* __restrict__ pos_emb) {
    int idx = blockIdx.x * 256 + threadIdx.x;
    if (idx < MM*EE) {
        int m = idx >> 9;
        int e = idx & (EE-1);
        int t = m % TT;
        float v = src_emb[(size_t)target[m]*EE + e] + pos_emb[(size_t)t*EE + e];
        g_emb[idx] = v;
        splitf(v, g_emb_h[idx], g_emb_l[idx]);
        return;
    }
    int j = idx - MM*EE;
    if (j < BB*2*HH) {
        int b = j >> 11;
        int r = (j >> 10) & 1;
        int h = j & (HH-1);
        size_t p = (size_t)(b*TP + r)*HH + h;
        g_xpad[p] = 0.f;
        g_xpad_h[p] = __float2bfloat16(0.f);
        g_xpad_l[p] = __float2bfloat16(0.f);
    }
}

__global__ void k_attcopy(float* __restrict__ dst) {
    int idx = blockIdx.x * 256 + threadIdx.x;
    if (idx < MM*SS) dst[idx] = g_att[idx];
}

// ---------------- fused attention: energy + softmax + att_enc (+split) ----------------
__global__ __launch_bounds__(256) void k_att(const float* __restrict__ encC,
                                             const float* __restrict__ encComb) {
    __shared__ float sE[32][104];
    const int w = threadIdx.x >> 5, lane = threadIdx.x & 31;
    const int mw = blockIdx.x * 32 + w * 4;
    const int b = mw / TT;

    float cr[4][16];
    #pragma unroll
    for (int r = 0; r < 4; r++) {
        const float4* cp = (const float4*)(g_comb + (size_t)(mw + r)*EE + lane*16);
        #pragma unroll
        for (int q = 0; q < 4; q++) {
            float4 v = cp[q];
            cr[r][q*4+0] = v.x; cr[r][q*4+1] = v.y; cr[r][q*4+2] = v.z; cr[r][q*4+3] = v.w;
        }
    }
    const float* ebase = encC + (size_t)b*SS*EE;
    for (int s = 0; s < SS; s++) {
        const float4* ep = (const float4*)(ebase + (size_t)s*EE + lane*16);
        float ev[16];
        #pragma unroll
        for (int q = 0; q < 4; q++) {
            float4 v = ep[q];
            ev[q*4+0] = v.x; ev[q*4+1] = v.y; ev[q*4+2] = v.z; ev[q*4+3] = v.w;
        }
        #pragma unroll
        for (int r = 0; r < 4; r++) {
            float p = 0.f;
            #pragma unroll
            for (int j = 0; j < 16; j++) p += cr[r][j] * ev[j];
            #pragma unroll
            for (int o = 16; o > 0; o >>= 1) p += __shfl_xor_sync(0xffffffffu, p, o);
            if (lane == 0) sE[w*4 + r][s] = p;
        }
    }
    __syncwarp();

    #pragma unroll
    for (int r = 0; r < 4; r++) {
        float v[4];
        #pragma unroll
        for (int q = 0; q < 4; q++) {
            int s = lane + 32*q;
            v[q] = (s < SS) ? sE[w*4 + r][s] : -FLT_MAX;
        }
        float mx = fmaxf(fmaxf(v[0], v[1]), fmaxf(v[2], v[3]));
        #pragma unroll
        for (int o = 16; o > 0; o >>= 1) mx = fmaxf(mx, __shfl_xor_sync(0xffffffffu, mx, o));
        float e[4]; float sm = 0.f;
        #pragma unroll
        for (int q = 0; q < 4; q++) {
            int s = lane + 32*q;
            e[q] = (s < SS) ? expf(v[q] - mx) : 0.f;
            sm += e[q];
        }
        #pragma unroll
        for (int o = 16; o > 0; o >>= 1) sm += __shfl_xor_sync(0xffffffffu, sm, o);
        float inv = 1.f / sm;
        #pragma unroll
        for (int q = 0; q < 4; q++) {
            int s = lane + 32*q;
            if (s < SS) {
                float a = e[q] * inv;
                sE[w*4 + r][s] = a;
                g_att[(size_t)(mw + r)*SS + s] = a;
            }
        }
    }
    __syncwarp();

    float acc[4][16];
    #pragma unroll
    for (int r = 0; r < 4; r++)
        #pragma unroll
        for (int j = 0; j < 16; j++) acc[r][j] = 0.f;
    const float* cbm = encComb + (size_t)b*SS*EE;
    for (int s = 0; s < SS; s++) {
        const float4* ep = (const float4*)(cbm + (size_t)s*EE + lane*16);
        float ev[16];
        #pragma unroll
        for (int q = 0; q < 4; q++) {
            float4 v = ep[q];
            ev[q*4+0] = v.x; ev[q*4+1] = v.y; ev[q*4+2] = v.z; ev[q*4+3] = v.w;
        }
        #pragma unroll
        for (int r = 0; r < 4; r++) {
            float a = sE[w*4 + r][s];
            #pragma unroll
            for (int j = 0; j < 16; j++) acc[r][j] += a * ev[j];
        }
    }
    #pragma unroll
    for (int r = 0; r < 4; r++) {
        size_t o = (size_t)(mw + r)*EE + lane*16;
        #pragma unroll
        for (int j = 0; j < 16; j++) splitf(acc[r][j], g_attenc_h[o+j], g_attenc_l[o+j]);
    }
}

// ---------------- tensor-core GEMM (bf16x3, 64x128 tile, SW64, 3-stage, 1 barrier/stage) ----------------
#define TMQ 64
#define TNQ 128
#define KT 32
#define A_H_OFF 0
#define A_L_OFF 4096
#define B_H_OFF 8192
#define B_L_OFF 16384
#define STAGE 24576
#define NSTG 3
#define DYN_BYTES (NSTG*STAGE + 128)

__device__ __forceinline__ uint32_t swz64(uint32_t x) { return x ^ ((x >> 3) & 0x30); }

__device__ __forceinline__ void ldsm4(uint32_t r[4], unsigned addr) {
    asm volatile("ldmatrix.sync.aligned.m8n8.x4.shared.b16 {%0,%1,%2,%3}, [%4];\n"
        : "=r"(r[0]), "=r"(r[1]), "=r"(r[2]), "=r"(r[3]) : "r"(addr));
}
__device__ __forceinline__ void mma16816(float c[4], const uint32_t a[4],
                                         uint32_t b0, uint32_t b1) {
    asm volatile(
        "mma.sync.aligned.m16n8k16.row.col.f32.bf16.bf16.f32 "
        "{%0,%1,%2,%3},{%4,%5,%6,%7},{%8,%9},{%0,%1,%2,%3};\n"
        : "+f"(c[0]), "+f"(c[1]), "+f"(c[2]), "+f"(c[3])
        : "r"(a[0]), "r"(a[1]), "r"(a[2]), "r"(a[3]), "r"(b0), "r"(b1));
}
__device__ __forceinline__ void cpasync16(uint32_t dst, const void* src) {
    asm volatile("cp.async.cg.shared.global [%0], [%1], 16;" :: "r"(dst), "l"(src) : "memory");
}
__device__ __forceinline__ void cp_commit() {
    asm volatile("cp.async.commit_group;" ::: "memory");
}
template<int N> __device__ __forceinline__ void cp_wait() {
    asm volatile("cp.async.wait_group %0;" :: "n"(N) : "memory");
}

__global__ __launch_bounds__(256, 3) void gemm_tc(
    const bf16* __restrict__ Ah, const bf16* __restrict__ Al, int amode, int lda,
    const bf16* __restrict__ Wh, const bf16* __restrict__ Wl,
    const float* __restrict__ bias, const float* __restrict__ add, int ldadd,
    float scale, float* __restrict__ C, bf16* __restrict__ Ch, bf16* __restrict__ Cl,
    int cmode, int ldc, int K, int emode,
    float* __restrict__ X, bf16* __restrict__ Xh, bf16* __restrict__ Xl)
{
    extern __shared__ char dynsm[];
    const int tid = threadIdx.x;
    const int lane = tid & 31, warp = tid >> 5;
    const int m0 = blockIdx.y * TMQ, n0 = blockIdx.x * TNQ;
    const unsigned sbase = ((unsigned)__cvta_generic_to_shared(dynsm) + 127u) & ~127u;

    // ---- load maps ----
    size_t a_go; uint32_t a_sd;
    {
        int row = tid >> 2, c = tid & 3;
        int m = m0 + row, rm = m;
        if (amode) { int b = m / TT, t = m - b*TT; rm = b*TP + t + ((amode == 1) ? 2 : 0); }
        a_go = (size_t)rm * lda + c * 8;
        a_sd = swz64((uint32_t)(row * 64 + c * 16));
    }
    size_t w_go[2]; uint32_t b_sd[2];
    #pragma unroll
    for (int i = 0; i < 2; i++) {
        int idx = tid + i * 256;
        int row = idx >> 2, c = idx & 3;
        w_go[i] = (size_t)(n0 + row) * K + c * 8;
        b_sd[i] = swz64((uint32_t)(row * 64 + c * 16));
    }

    const int wm = warp & 1;
    const int wn = warp >> 1;

    // precomputed swizzled fragment bases.
    // NOTE: swz64(lin + kof) == swz64(lin) ^ kof for kof in {0,32}, because the
    // sub-row offset of lin has bit5==0 (so lin+kof == lin^kof, mask bits 7-8 unchanged).
    // (ADD is WRONG here: the swizzle may flip bit5, and +32 would carry into bit6.)
    uint32_t a_sw[2], b_sw[2];
    #pragma unroll
    for (int tm = 0; tm < 2; tm++)
        a_sw[tm] = swz64((uint32_t)((wm*32 + tm*16 + (lane & 15)) * 64 + (lane >> 4) * 16));
    #pragma unroll
    for (int tb = 0; tb < 2; tb++)
        b_sw[tb] = swz64((uint32_t)((wn*32 + tb*16 + (lane & 7) + ((lane >> 4) << 3)) * 64
                                    + (((lane >> 3) & 1) << 4)));

    float acc[2][4][4];
    #pragma unroll
    for (int i = 0; i < 2; i++)
        #pragma unroll
        for (int j = 0; j < 4; j++)
            #pragma unroll
            for (int q = 0; q < 4; q++) acc[i][j][q] = 0.f;

    const int nK = K / KT;

    #define ISSUE_STAGE(s) do {                                               \
        const size_t k0_ = (size_t)(s) * KT;                                  \
        const unsigned stg_ = sbase + (unsigned)(((s) % NSTG) * STAGE);       \
        cpasync16(stg_ + A_H_OFF + a_sd, Ah + a_go + k0_);                    \
        cpasync16(stg_ + A_L_OFF + a_sd, Al + a_go + k0_);                    \
        _Pragma("unroll")                                                     \
        for (int i_ = 0; i_ < 2; i_++) {                                      \
            cpasync16(stg_ + B_H_OFF + b_sd[i_], Wh + w_go[i_] + k0_);        \
            cpasync16(stg_ + B_L_OFF + b_sd[i_], Wl + w_go[i_] + k0_);        \
        }                                                                     \
        cp_commit();                                                          \
    } while (0)

    ISSUE_STAGE(0); ISSUE_STAGE(1);
    for (int s = 0; s < nK; s++) {
        if (s == nK - 1) cp_wait<0>(); else cp_wait<1>();
        __syncthreads();          // publishes stage s; proves consumers of s-1 done

        const unsigned bufb = sbase + (unsigned)((s % NSTG) * STAGE);
        #pragma unroll
        for (int kk = 0; kk < 2; kk++) {
            const unsigned kof = kk * 32;
            uint32_t ah[2][4], al[2][4], bh[2][4], bl[2][4];
            #pragma unroll
            for (int tm = 0; tm < 2; tm++) {
                ldsm4(ah[tm], bufb + A_H_OFF + (a_sw[tm] ^ kof));
                ldsm4(al[tm], bufb + A_L_OFF + (a_sw[tm] ^ kof));
            }
            #pragma unroll
            for (int tb = 0; tb < 2; tb++) {
                ldsm4(bh[tb], bufb + B_H_OFF + (b_sw[tb] ^ kof));
                ldsm4(bl[tb], bufb + B_L_OFF + (b_sw[tb] ^ kof));
            }
            // hi*hi
            #pragma unroll
            for (int tm = 0; tm < 2; tm++)
                #pragma unroll
                for (int j = 0; j < 4; j++)
                    mma16816(acc[tm][j], ah[tm], bh[j>>1][(j&1)*2], bh[j>>1][(j&1)*2+1]);
            // lo*hi
            #pragma unroll
            for (int tm = 0; tm < 2; tm++)
                #pragma unroll
                for (int j = 0; j < 4; j++)
                    mma16816(acc[tm][j], al[tm], bh[j>>1][(j&1)*2], bh[j>>1][(j&1)*2+1]);
            // hi*lo
            #pragma unroll
            for (int tm = 0; tm < 2; tm++)
                #pragma unroll
                for (int j = 0; j < 4; j++)
                    mma16816(acc[tm][j], ah[tm], bl[j>>1][(j&1)*2], bl[j>>1][(j&1)*2+1]);
        }
        // prefetch into buf (s-1)%3, freed by this iteration's top barrier;
        // issued after compute so it overlaps other warps' MMA work
        if (s + 2 < nK) ISSUE_STAGE(s + 2);
    }
    #undef ISSUE_STAGE

    // ---------------- epilogue ----------------
    #pragma unroll
    for (int tm = 0; tm < 2; tm++) {
        #pragma unroll
        for (int half = 0; half < 2; half++) {
            int m = m0 + wm*32 + tm*16 + (lane >> 2) + half*8;
            int rm = m;
            if (cmode == 1) { int b = m / TT, t = m - b*TT; rm = b*TP + t + 2; }
            int rmp = 0;
            if (emode == 2) { int b = m / TT, t = m - b*TT; rmp = b*TP + t + 2; }
            size_t crow = (size_t)rm * ldc;
            size_t arow = (size_t)m * ldadd;
            #pragma unroll
            for (int j = 0; j < 4; j++) {
                int n = n0 + wn*32 + j*8 + (lane & 3)*2;
                float v0 = acc[tm][j][half*2 + 0];
                float v1 = acc[tm][j][half*2 + 1];
                if (bias) { v0 += bias[n]; v1 += bias[n+1]; }
                if (emode == 1) {
                    float g = v0 / (1.f + expf(-v1));
                    int h = n >> 1;
                    C[crow + h] = g;
                    splitf(g, Ch[crow + h], Cl[crow + h]);
                } else {
                    if (add) { v0 += add[arow + n]; v1 += add[arow + n + 1]; }
                    v0 *= scale; v1 *= scale;
                    float2 r; r.x = v0; r.y = v1;
                    *(float2*)(C + crow + n) = r;
                    if (Ch) {
                        __nv_bfloat162 hv, lv;
                        splitf(v0, hv.x, lv.x);
                        splitf(v1, hv.y, lv.y);
                        *(__nv_bfloat162*)(Ch + crow + n) = hv;
                        *(__nv_bfloat162*)(Cl + crow + n) = lv;
                    }
                    if (emode == 2) {
                        size_t xrow = (size_t)rmp * ldc;
                        float x0 = (v0 + X[xrow + n]) * scale;
                        float x1 = (v1 + X[xrow + n + 1]) * scale;
                        float2 xr; xr.x = x0; xr.y = x1;
                        *(float2*)(X + xrow + n) = xr;
                        __nv_bfloat162 hv, lv;
                        splitf(x0, hv.x, lv.x);
                        splitf(x1, hv.y, lv.y);
                        *(__nv_bfloat162*)(Xh + xrow + n) = hv;
                        *(__nv_bfloat162*)(Xl + xrow + n) = lv;
                    }
                }
            }
        }
    }
}

static void launch_tc(const bf16* Ah, const bf16* Al, int amode, int lda,
                      const bf16* Wh, const bf16* Wl,
                      const float* bias, const float* add, int ldadd, float scale,
                      float* C, bf16* Ch, bf16* Cl, int cmode, int ldc,
                      int M, int N, int K, int emode = 0,
                      float* X = nullptr, bf16* Xh = nullptr, bf16* Xl = nullptr) {
    dim3 g(N / TNQ, M / TMQ);
    gemm_tc<<<g, 256, DYN_BYTES>>>(Ah, Al, amode, lda, Wh, Wl, bias, add, ldadd,
                                   scale, C, Ch, Cl, cmode, ldc, K, emode, X, Xh, Xl);
}

// ---------------- launch ----------------
extern "C" void kernel_launch(void* const* d_in, const int* in_sizes, int n_in,
                              void* d_out, int out_size) {
    const int*   target   = (const int*)  d_in[0];
    const float* encC     = (const float*)d_in[1];
    const float* encComb  = (const float*)d_in[2];
    const float* src_emb  = (const float*)d_in[3];
    const float* pos_emb  = (const float*)d_in[4];
    const float* w_eh     = (const float*)d_in[5];
    const float* b_eh     = (const float*)d_in[6];
    const float* w_he     = (const float*)d_in[7];
    const float* b_he     = (const float*)d_in[8];
    const float* w_ahe    = (const float*)d_in[9];
    const float* b_ahe    = (const float*)d_in[10];
    const float* w_aeh    = (const float*)d_in[11];
    const float* b_aeh    = (const float*)d_in[12];
    const float* w_fc     = (const float*)d_in[13];
    const float* b_fc     = (const float*)d_in[14];
    const float* conv_w   = (const float*)d_in[15];
    const float* conv_b   = (const float*)d_in[16];
    float* out = (float*)d_out;

    cudaFuncSetAttribute(gemm_tc, cudaFuncAttributeMaxDynamicSharedMemorySize, DYN_BYTES);

    float *p_xpad, *p_emb, *p_conved, *p_comb, *p_cbias;
    bf16 *p_wt_h, *p_wt_l, *p_weh_h, *p_weh_l, *p_whe_h, *p_whe_l;
    bf16 *p_wahe_h, *p_wahe_l, *p_waeh_h, *p_waeh_l, *p_wfc_h, *p_wfc_l;
    bf16 *p_xpad_h, *p_xpad_l, *p_emb_h, *p_emb_l, *p_conved_h, *p_conved_l;
    bf16 *p_attenc_h, *p_attenc_l, *p_comb_h, *p_comb_l;
    cudaGetSymbolAddress((void**)&p_xpad, g_xpad);
    cudaGetSymbolAddress((void**)&p_emb, g_emb);
    cudaGetSymbolAddress((void**)&p_conved, g_conved);
    cudaGetSymbolAddress((void**)&p_comb, g_comb);
    cudaGetSymbolAddress((void**)&p_cbias, g_cbias);
    cudaGetSymbolAddress((void**)&p_wt_h, g_wt_h);   cudaGetSymbolAddress((void**)&p_wt_l, g_wt_l);
    cudaGetSymbolAddress((void**)&p_weh_h, g_weh_h); cudaGetSymbolAddress((void**)&p_weh_l, g_weh_l);
    cudaGetSymbolAddress((void**)&p_whe_h, g_whe_h); cudaGetSymbolAddress((void**)&p_whe_l, g_whe_l);
    cudaGetSymbolAddress((void**)&p_wahe_h, g_wahe_h); cudaGetSymbolAddress((void**)&p_wahe_l, g_wahe_l);
    cudaGetSymbolAddress((void**)&p_waeh_h, g_waeh_h); cudaGetSymbolAddress((void**)&p_waeh_l, g_waeh_l);
    cudaGetSymbolAddress((void**)&p_wfc_h, g_wfc_h); cudaGetSymbolAddress((void**)&p_wfc_l, g_wfc_l);
    cudaGetSymbolAddress((void**)&p_xpad_h, g_xpad_h); cudaGetSymbolAddress((void**)&p_xpad_l, g_xpad_l);
    cudaGetSymbolAddress((void**)&p_emb_h, g_emb_h); cudaGetSymbolAddress((void**)&p_emb_l, g_emb_l);
    cudaGetSymbolAddress((void**)&p_conved_h, g_conved_h); cudaGetSymbolAddress((void**)&p_conved_l, g_conved_l);
    cudaGetSymbolAddress((void**)&p_attenc_h, g_attenc_h); cudaGetSymbolAddress((void**)&p_attenc_l, g_attenc_l);
    cudaGetSymbolAddress((void**)&p_comb_h, g_comb_h); cudaGetSymbolAddress((void**)&p_comb_l, g_comb_l);

    const float SC = 0.7071067811865476f;

    k_prep<<<(unsigned)((PREP_TOTAL + 255) / 256), 256>>>(
        conv_w, conv_b, w_eh, w_he, w_ahe, w_aeh, w_fc);
    k_embed<<<(MM*EE + BB*2*HH + 255) / 256, 256>>>(target, src_emb, pos_emb);

    launch_tc(p_emb_h, p_emb_l, 0, EE, p_weh_h, p_weh_l, b_eh, nullptr, 0, 1.f,
              p_xpad, p_xpad_h, p_xpad_l, 1, HH, MM, HH, EE);

    for (int l = 0; l < LL; l++) {
        const size_t wo = (size_t)l*2*HH*3*HH;
        launch_tc(p_xpad_h, p_xpad_l, 2, HH, p_wt_h + wo, p_wt_l + wo,
                  p_cbias + (size_t)l*2*HH, nullptr, 0, 1.f,
                  p_conved, p_conved_h, p_conved_l, 0, HH, MM, 2*HH, 3*HH, 1);
        launch_tc(p_conved_h, p_conved_l, 0, HH, p_wahe_h, p_wahe_l,
                  b_ahe, p_emb, EE, SC, p_comb, nullptr, nullptr, 0, EE, MM, EE, HH);
        k_att<<<MM/32, 256>>>(encC, encComb);
        launch_tc(p_attenc_h, p_attenc_l, 0, EE, p_waeh_h, p_waeh_l,
                  b_aeh, p_conved, HH, SC, p_conved, p_conved_h, p_conved_l,
                  0, HH, MM, HH, EE, 2, p_xpad, p_xpad_h, p_xpad_l);
    }

    launch_tc(p_xpad_h, p_xpad_l, 1, HH, p_whe_h, p_whe_l, b_he, nullptr, 0, 1.f,
              p_comb, p_comb_h, p_comb_l, 0, EE, MM, EE, HH);
    launch_tc(p_comb_h, p_comb_l, 0, EE, p_wfc_h, p_wfc_l, b_fc, nullptr, 0, 1.f,
              out, nullptr, nullptr, 0, VV, MM, VV, EE);

    const long long ATT_OFF = (long long)MM * VV;
    if ((long long)out_size >= ATT_OFF + (long long)MM*SS) {
        k_attcopy<<<(MM*SS + 255) / 256, 256>>>(out + ATT_OFF);
    }
}

// round 17
// speedup vs baseline: 1.4675x; 1.3881x over previous
#include <cuda_runtime.h>
#include <cuda_fp16.h>
#include <math.h>
#include <float.h>
#include <stdint.h>

// Problem dims
#define BB 32
#define TT 100
#define SS 100
#define EE 512
#define HH 1024
#define LL 10
#define VV 32000
#define MM (BB*TT)        // 3200
#define TP (TT+2)         // 102 (left-pad 2)

typedef __half hf;

// ---------------- scratch (static device memory; no allocation) ----------------
__device__ float g_xpad[(size_t)BB*TP*HH];
__device__ float g_emb[(size_t)MM*EE];
__device__ float g_conved[(size_t)MM*HH];
__device__ float g_comb[(size_t)MM*EE];
__device__ float g_att[(size_t)MM*SS];
__device__ float g_cbias[(size_t)LL*2*HH];

// weights: fp16 hi only (B side of GEMM; error = A*Bl ~ 2^-11.8, within 1e-3 budget)
__device__ hf g_wt[(size_t)LL*2*HH*3*HH];
__device__ hf g_weh[(size_t)HH*EE];
__device__ hf g_whe[(size_t)EE*HH];
__device__ hf g_wahe[(size_t)EE*HH];
__device__ hf g_waeh[(size_t)HH*EE];
__device__ hf g_wfc[(size_t)VV*EE];
// activations: fp16 hi/lo pairs (A side)
__device__ hf g_xpad_h[(size_t)BB*TP*HH], g_xpad_l[(size_t)BB*TP*HH];
__device__ hf g_emb_h[(size_t)MM*EE],     g_emb_l[(size_t)MM*EE];
__device__ hf g_conved_h[(size_t)MM*HH],  g_conved_l[(size_t)MM*HH];
__device__ hf g_attenc_h[(size_t)MM*EE],  g_attenc_l[(size_t)MM*EE];
__device__ hf g_comb_h[(size_t)MM*EE],    g_comb_l[(size_t)MM*EE];

__device__ __forceinline__ void splitf(float v, hf& h, hf& l) {
    hf hh = __float2half_rn(v);
    h = hh;
    l = __float2half_rn(v - __half2float(hh));
}

// ---------------- prep: ONE kernel for all weight prep ----------------
#define WT_TOTAL ((size_t)LL*2*HH*3*HH)
#define PREP_REST_TOTAL ((size_t)LL*2*HH + 4*(size_t)HH*EE + (size_t)VV*EE)
#define PREP_TOTAL (WT_TOTAL + PREP_REST_TOTAL)

__global__ void k_prep(const float* __restrict__ w, const float* __restrict__ cb,
                       const float* __restrict__ w_eh, const float* __restrict__ w_he,
                       const float* __restrict__ w_ahe, const float* __restrict__ w_aeh,
                       const float* __restrict__ w_fc) {
    size_t idx = (size_t)blockIdx.x * 256 + threadIdx.x;
    if (idx < WT_TOTAL) {
        // conv_w [L][2H][H][3] -> wt [L][n'][3][H], n' interleaved (2h = a_h, 2h+1 = g_h)
        int h = (int)(idx & (HH-1));
        size_t r = idx >> 10;
        int k = (int)(r % 3);
        size_t ln = r / 3;
        int np = (int)(ln & (2*HH - 1));
        size_t l = ln >> 11;
        int o = (np & 1) ? (HH + (np >> 1)) : (np >> 1);
        g_wt[idx] = __float2half_rn(w[(l*2*HH + o)*3*HH + (size_t)h*3 + k]);
        return;
    }
    idx -= WT_TOTAL;
    const size_t NB = (size_t)LL*2*HH;
    const size_t NW = (size_t)HH*EE;
    if (idx < NB) {
        int np = (int)(idx & (2*HH - 1));
        int l = (int)(idx >> 11);
        int o = (np & 1) ? (HH + (np >> 1)) : (np >> 1);
        g_cbias[idx] = cb[(size_t)l*2*HH + o];
        return;
    }
    idx -= NB;
    if (idx < NW) { g_weh[idx]  = __float2half_rn(w_eh[idx]);  return; }
    idx -= NW;
    if (idx < NW) { g_whe[idx]  = __float2half_rn(w_he[idx]);  return; }
    idx -= NW;
    if (idx < NW) { g_wahe[idx] = __float2half_rn(w_ahe[idx]); return; }
    idx -= NW;
    if (idx < NW) { g_waeh[idx] = __float2half_rn(w_aeh[idx]); return; }
    idx -= NW;
    if (idx < (size_t)VV*EE) { g_wfc[idx] = __float2half_rn(w_fc[idx]); }
}

__global__ void k_embed(const int* __restrict__ target,
                        const float* __restrict__ src_emb,
                        const float* __restrict__ pos_emb) {
    int idx = blockIdx.x * 256 + threadIdx.x;
    if (idx < MM*EE) {
        int m = idx >> 9;
        int e = idx & (EE-1);
        int t = m % TT;
        float v = src_emb[(size_t)target[m]*EE + e] + pos_emb[(size_t)t*EE + e];
        g_emb[idx] = v;
        splitf(v, g_emb_h[idx], g_emb_l[idx]);
        return;
    }
    int j = idx - MM*EE;
    if (j < BB*2*HH) {
        int b = j >> 11;
        int r = (j >> 10) & 1;
        int h = j & (HH-1);
        size_t p = (size_t)(b*TP + r)*HH + h;
        g_xpad[p] = 0.f;
        g_xpad_h[p] = __float2half_rn(0.f);
        g_xpad_l[p] = __float2half_rn(0.f);
    }
}

__global__ void k_attcopy(float* __restrict__ dst) {
    int idx = blockIdx.x * 256 + threadIdx.x;
    if (idx < MM*SS) dst[idx] = g_att[idx];
}

// ---------------- fused attention: energy + softmax + att_enc (+split) ----------------
__global__ __launch_bounds__(256) void k_att(const float* __restrict__ encC,
                                             const float* __restrict__ encComb) {
    __shared__ float sE[32][104];
    const int w = threadIdx.x >> 5, lane = threadIdx.x & 31;
    const int mw = blockIdx.x * 32 + w * 4;
    const int b = mw / TT;

    float cr[4][16];
    #pragma unroll
    for (int r = 0; r < 4; r++) {
        const float4* cp = (const float4*)(g_comb + (size_t)(mw + r)*EE + lane*16);
        #pragma unroll
        for (int q = 0; q < 4; q++) {
            float4 v = cp[q];
            cr[r][q*4+0] = v.x; cr[r][q*4+1] = v.y; cr[r][q*4+2] = v.z; cr[r][q*4+3] = v.w;
        }
    }
    const float* ebase = encC + (size_t)b*SS*EE;
    for (int s = 0; s < SS; s++) {
        const float4* ep = (const float4*)(ebase + (size_t)s*EE + lane*16);
        float ev[16];
        #pragma unroll
        for (int q = 0; q < 4; q++) {
            float4 v = ep[q];
            ev[q*4+0] = v.x; ev[q*4+1] = v.y; ev[q*4+2] = v.z; ev[q*4+3] = v.w;
        }
        #pragma unroll
        for (int r = 0; r < 4; r++) {
            float p = 0.f;
            #pragma unroll
            for (int j = 0; j < 16; j++) p += cr[r][j] * ev[j];
            #pragma unroll
            for (int o = 16; o > 0; o >>= 1) p += __shfl_xor_sync(0xffffffffu, p, o);
            if (lane == 0) sE[w*4 + r][s] = p;
        }
    }
    __syncwarp();

    #pragma unroll
    for (int r = 0; r < 4; r++) {
        float v[4];
        #pragma unroll
        for (int q = 0; q < 4; q++) {
            int s = lane + 32*q;
            v[q] = (s < SS) ? sE[w*4 + r][s] : -FLT_MAX;
        }
        float mx = fmaxf(fmaxf(v[0], v[1]), fmaxf(v[2], v[3]));
        #pragma unroll
        for (int o = 16; o > 0; o >>= 1) mx = fmaxf(mx, __shfl_xor_sync(0xffffffffu, mx, o));
        float e[4]; float sm = 0.f;
        #pragma unroll
        for (int q = 0; q < 4; q++) {
            int s = lane + 32*q;
            e[q] = (s < SS) ? expf(v[q] - mx) : 0.f;
            sm += e[q];
        }
        #pragma unroll
        for (int o = 16; o > 0; o >>= 1) sm += __shfl_xor_sync(0xffffffffu, sm, o);
        float inv = 1.f / sm;
        #pragma unroll
        for (int q = 0; q < 4; q++) {
            int s = lane + 32*q;
            if (s < SS) {
                float a = e[q] * inv;
                sE[w*4 + r][s] = a;
                g_att[(size_t)(mw + r)*SS + s] = a;
            }
        }
    }
    __syncwarp();

    float acc[4][16];
    #pragma unroll
    for (int r = 0; r < 4; r++)
        #pragma unroll
        for (int j = 0; j < 16; j++) acc[r][j] = 0.f;
    const float* cbm = encComb + (size_t)b*SS*EE;
    for (int s = 0; s < SS; s++) {
        const float4* ep = (const float4*)(cbm + (size_t)s*EE + lane*16);
        float ev[16];
        #pragma unroll
        for (int q = 0; q < 4; q++) {
            float4 v = ep[q];
            ev[q*4+0] = v.x; ev[q*4+1] = v.y; ev[q*4+2] = v.z; ev[q*4+3] = v.w;
        }
        #pragma unroll
        for (int r = 0; r < 4; r++) {
            float a = sE[w*4 + r][s];
            #pragma unroll
            for (int j = 0; j < 16; j++) acc[r][j] += a * ev[j];
        }
    }
    #pragma unroll
    for (int r = 0; r < 4; r++) {
        size_t o = (size_t)(mw + r)*EE + lane*16;
        #pragma unroll
        for (int j = 0; j < 16; j++) splitf(acc[r][j], g_attenc_h[o+j], g_attenc_l[o+j]);
    }
}

// ---------------- tensor-core GEMM (fp16x2: (Ah+Al)*Bh, 64x128 tile, SW64, 4-stage) ----------------
// emode 0: C = scale*(acc + bias + add)            [+ optional split Ch/Cl]
// emode 1: GLU on interleaved column pairs: conved[m][n/2] = a*sigmoid(g)  (+ split)
// emode 2: v = scale*(acc+bias+add); C=v (+split); X[pad] = scale*(v + X[pad]) (+split)
// amode: 0 identity row, 1 padded(+2) row, 2 conv row (padded, no +2, K spans 3 rows)

#define TMQ 64
#define TNQ 128
#define KT 32
#define A_H_OFF 0
#define A_L_OFF 4096
#define B_H_OFF 8192
#define STAGE 16384
#define NSTG 4
#define DYN_BYTES (NSTG*STAGE + 128)

__device__ __forceinline__ uint32_t swz64(uint32_t x) { return x ^ ((x >> 3) & 0x30); }

__device__ __forceinline__ void ldsm4(uint32_t r[4], unsigned addr) {
    asm volatile("ldmatrix.sync.aligned.m8n8.x4.shared.b16 {%0,%1,%2,%3}, [%4];\n"
        : "=r"(r[0]), "=r"(r[1]), "=r"(r[2]), "=r"(r[3]) : "r"(addr));
}
__device__ __forceinline__ void mma16816(float c[4], const uint32_t a[4],
                                         uint32_t b0, uint32_t b1) {
    asm volatile(
        "mma.sync.aligned.m16n8k16.row.col.f32.f16.f16.f32 "
        "{%0,%1,%2,%3},{%4,%5,%6,%7},{%8,%9},{%0,%1,%2,%3};\n"
        : "+f"(c[0]), "+f"(c[1]), "+f"(c[2]), "+f"(c[3])
        : "r"(a[0]), "r"(a[1]), "r"(a[2]), "r"(a[3]), "r"(b0), "r"(b1));
}
__device__ __forceinline__ void cpasync16(uint32_t dst, const void* src) {
    asm volatile("cp.async.cg.shared.global [%0], [%1], 16;" :: "r"(dst), "l"(src) : "memory");
}
__device__ __forceinline__ void cp_commit() {
    asm volatile("cp.async.commit_group;" ::: "memory");
}
template<int N> __device__ __forceinline__ void cp_wait() {
    asm volatile("cp.async.wait_group %0;" :: "n"(N) : "memory");
}

__global__ __launch_bounds__(256, 3) void gemm_tc(
    const hf* __restrict__ Ah, const hf* __restrict__ Al, int amode, int lda,
    const hf* __restrict__ Wh,
    const float* __restrict__ bias, const float* __restrict__ add, int ldadd,
    float scale, float* __restrict__ C, hf* __restrict__ Ch, hf* __restrict__ Cl,
    int cmode, int ldc, int K, int emode,
    float* __restrict__ X, hf* __restrict__ Xh, hf* __restrict__ Xl)
{
    extern __shared__ char dynsm[];
    const int tid = threadIdx.x;
    const int lane = tid & 31, warp = tid >> 5;
    const int m0 = blockIdx.y * TMQ, n0 = blockIdx.x * TNQ;
    const unsigned sbase = ((unsigned)__cvta_generic_to_shared(dynsm) + 127u) & ~127u;

    // ---- load maps ----
    size_t a_go; uint32_t a_sd;
    {
        int row = tid >> 2, c = tid & 3;
        int m = m0 + row, rm = m;
        if (amode) { int b = m / TT, t = m - b*TT; rm = b*TP + t + ((amode == 1) ? 2 : 0); }
        a_go = (size_t)rm * lda + c * 8;
        a_sd = swz64((uint32_t)(row * 64 + c * 16));
    }
    size_t w_go[2]; uint32_t b_sd[2];
    #pragma unroll
    for (int i = 0; i < 2; i++) {
        int idx = tid + i * 256;
        int row = idx >> 2, c = idx & 3;
        w_go[i] = (size_t)(n0 + row) * K + c * 8;
        b_sd[i] = swz64((uint32_t)(row * 64 + c * 16));
    }

    const int wm = warp & 1;
    const int wn = warp >> 1;

    // precomputed swizzled fragment bases; swz64(lin+kof) == swz64(lin) ^ kof for kof in {0,32}
    uint32_t a_sw[2], b_sw[2];
    #pragma unroll
    for (int tm = 0; tm < 2; tm++)
        a_sw[tm] = swz64((uint32_t)((wm*32 + tm*16 + (lane & 15)) * 64 + (lane >> 4) * 16));
    #pragma unroll
    for (int tb = 0; tb < 2; tb++)
        b_sw[tb] = swz64((uint32_t)((wn*32 + tb*16 + (lane & 7) + ((lane >> 4) << 3)) * 64
                                    + (((lane >> 3) & 1) << 4)));

    float acc[2][4][4];
    #pragma unroll
    for (int i = 0; i < 2; i++)
        #pragma unroll
        for (int j = 0; j < 4; j++)
            #pragma unroll
            for (int q = 0; q < 4; q++) acc[i][j][q] = 0.f;

    const int nK = K / KT;

    #define ISSUE_STAGE(s) do {                                               \
        const size_t k0_ = (size_t)(s) * KT;                                  \
        const unsigned stg_ = sbase + (unsigned)(((s) % NSTG) * STAGE);       \
        cpasync16(stg_ + A_H_OFF + a_sd, Ah + a_go + k0_);                    \
        cpasync16(stg_ + A_L_OFF + a_sd, Al + a_go + k0_);                    \
        _Pragma("unroll")                                                     \
        for (int i_ = 0; i_ < 2; i_++)                                        \
            cpasync16(stg_ + B_H_OFF + b_sd[i_], Wh + w_go[i_] + k0_);        \
        cp_commit();                                                          \
    } while (0)

    ISSUE_STAGE(0); ISSUE_STAGE(1); ISSUE_STAGE(2);   // nK >= 16 always
    for (int s = 0; s < nK; s++) {
        if (s >= nK - 2) cp_wait<0>(); else cp_wait<2>();
        __syncthreads();          // publishes stage s; proves consumers of s-2 done

        const unsigned bufb = sbase + (unsigned)((s % NSTG) * STAGE);
        #pragma unroll
        for (int kk = 0; kk < 2; kk++) {
            const unsigned kof = kk * 32;
            uint32_t ah[2][4], al[2][4], bh[2][4];
            #pragma unroll
            for (int tm = 0; tm < 2; tm++) {
                ldsm4(ah[tm], bufb + A_H_OFF + (a_sw[tm] ^ kof));
                ldsm4(al[tm], bufb + A_L_OFF + (a_sw[tm] ^ kof));
            }
            #pragma unroll
            for (int tb = 0; tb < 2; tb++)
                ldsm4(bh[tb], bufb + B_H_OFF + (b_sw[tb] ^ kof));
            // hi*hi
            #pragma unroll
            for (int tm = 0; tm < 2; tm++)
                #pragma unroll
                for (int j = 0; j < 4; j++)
                    mma16816(acc[tm][j], ah[tm], bh[j>>1][(j&1)*2], bh[j>>1][(j&1)*2+1]);
            // lo*hi
            #pragma unroll
            for (int tm = 0; tm < 2; tm++)
                #pragma unroll
                for (int j = 0; j < 4; j++)
                    mma16816(acc[tm][j], al[tm], bh[j>>1][(j&1)*2], bh[j>>1][(j&1)*2+1]);
        }
        // prefetch into buf (s-2)%4 (freed by this iteration's top barrier at 4 stages);
        // issued after compute to overlap other warps' MMA work
        if (s + 3 < nK) ISSUE_STAGE(s + 3);
    }
    #undef ISSUE_STAGE

    // ---------------- epilogue ----------------
    #pragma unroll
    for (int tm = 0; tm < 2; tm++) {
        #pragma unroll
        for (int half = 0; half < 2; half++) {
            int m = m0 + wm*32 + tm*16 + (lane >> 2) + half*8;
            int rm = m;
            if (cmode == 1) { int b = m / TT, t = m - b*TT; rm = b*TP + t + 2; }
            int rmp = 0;
            if (emode == 2) { int b = m / TT, t = m - b*TT; rmp = b*TP + t + 2; }
            size_t crow = (size_t)rm * ldc;
            size_t arow = (size_t)m * ldadd;
            #pragma unroll
            for (int j = 0; j < 4; j++) {
                int n = n0 + wn*32 + j*8 + (lane & 3)*2;
                float v0 = acc[tm][j][half*2 + 0];
                float v1 = acc[tm][j][half*2 + 1];
                if (bias) { v0 += bias[n]; v1 += bias[n+1]; }
                if (emode == 1) {
                    float g = v0 / (1.f + expf(-v1));
                    int h = n >> 1;
                    C[crow + h] = g;
                    splitf(g, Ch[crow + h], Cl[crow + h]);
                } else {
                    if (add) { v0 += add[arow + n]; v1 += add[arow + n + 1]; }
                    v0 *= scale; v1 *= scale;
                    float2 r; r.x = v0; r.y = v1;
                    *(float2*)(C + crow + n) = r;
                    if (Ch) {
                        __half2 hv, lv;
                        splitf(v0, hv.x, lv.x);
                        splitf(v1, hv.y, lv.y);
                        *(__half2*)(Ch + crow + n) = hv;
                        *(__half2*)(Cl + crow + n) = lv;
                    }
                    if (emode == 2) {
                        size_t xrow = (size_t)rmp * ldc;
                        float x0 = (v0 + X[xrow + n]) * scale;
                        float x1 = (v1 + X[xrow + n + 1]) * scale;
                        float2 xr; xr.x = x0; xr.y = x1;
                        *(float2*)(X + xrow + n) = xr;
                        __half2 hv, lv;
                        splitf(x0, hv.x, lv.x);
                        splitf(x1, hv.y, lv.y);
                        *(__half2*)(Xh + xrow + n) = hv;
                        *(__half2*)(Xl + xrow + n) = lv;
                    }
                }
            }
        }
    }
}

static void launch_tc(const hf* Ah, const hf* Al, int amode, int lda,
                      const hf* Wh,
                      const float* bias, const float* add, int ldadd, float scale,
                      float* C, hf* Ch, hf* Cl, int cmode, int ldc,
                      int M, int N, int K, int emode = 0,
                      float* X = nullptr, hf* Xh = nullptr, hf* Xl = nullptr) {
    dim3 g(N / TNQ, M / TMQ);
    gemm_tc<<<g, 256, DYN_BYTES>>>(Ah, Al, amode, lda, Wh, bias, add, ldadd,
                                   scale, C, Ch, Cl, cmode, ldc, K, emode, X, Xh, Xl);
}

// ---------------- launch ----------------
extern "C" void kernel_launch(void* const* d_in, const int* in_sizes, int n_in,
                              void* d_out, int out_size) {
    const int*   target   = (const int*)  d_in[0];
    const float* encC     = (const float*)d_in[1];
    const float* encComb  = (const float*)d_in[2];
    const float* src_emb  = (const float*)d_in[3];
    const float* pos_emb  = (const float*)d_in[4];
    const float* w_eh     = (const float*)d_in[5];
    const float* b_eh     = (const float*)d_in[6];
    const float* w_he     = (const float*)d_in[7];
    const float* b_he     = (const float*)d_in[8];
    const float* w_ahe    = (const float*)d_in[9];
    const float* b_ahe    = (const float*)d_in[10];
    const float* w_aeh    = (const float*)d_in[11];
    const float* b_aeh    = (const float*)d_in[12];
    const float* w_fc     = (const float*)d_in[13];
    const float* b_fc     = (const float*)d_in[14];
    const float* conv_w   = (const float*)d_in[15];
    const float* conv_b   = (const float*)d_in[16];
    float* out = (float*)d_out;

    cudaFuncSetAttribute(gemm_tc, cudaFuncAttributeMaxDynamicSharedMemorySize, DYN_BYTES);

    float *p_xpad, *p_emb, *p_conved, *p_comb, *p_cbias;
    hf *p_wt, *p_weh, *p_whe, *p_wahe, *p_waeh, *p_wfc;
    hf *p_xpad_h, *p_xpad_l, *p_emb_h, *p_emb_l, *p_conved_h, *p_conved_l;
    hf *p_attenc_h, *p_attenc_l, *p_comb_h, *p_comb_l;
    cudaGetSymbolAddress((void**)&p_xpad, g_xpad);
    cudaGetSymbolAddress((void**)&p_emb, g_emb);
    cudaGetSymbolAddress((void**)&p_conved, g_conved);
    cudaGetSymbolAddress((void**)&p_comb, g_comb);
    cudaGetSymbolAddress((void**)&p_cbias, g_cbias);
    cudaGetSymbolAddress((void**)&p_wt, g_wt);
    cudaGetSymbolAddress((void**)&p_weh, g_weh);
    cudaGetSymbolAddress((void**)&p_whe, g_whe);
    cudaGetSymbolAddress((void**)&p_wahe, g_wahe);
    cudaGetSymbolAddress((void**)&p_waeh, g_waeh);
    cudaGetSymbolAddress((void**)&p_wfc, g_wfc);
    cudaGetSymbolAddress((void**)&p_xpad_h, g_xpad_h); cudaGetSymbolAddress((void**)&p_xpad_l, g_xpad_l);
    cudaGetSymbolAddress((void**)&p_emb_h, g_emb_h); cudaGetSymbolAddress((void**)&p_emb_l, g_emb_l);
    cudaGetSymbolAddress((void**)&p_conved_h, g_conved_h); cudaGetSymbolAddress((void**)&p_conved_l, g_conved_l);
    cudaGetSymbolAddress((void**)&p_attenc_h, g_attenc_h); cudaGetSymbolAddress((void**)&p_attenc_l, g_attenc_l);
    cudaGetSymbolAddress((void**)&p_comb_h, g_comb_h); cudaGetSymbolAddress((void**)&p_comb_l, g_comb_l);

    const float SC = 0.7071067811865476f;

    k_prep<<<(unsigned)((PREP_TOTAL + 255) / 256), 256>>>(
        conv_w, conv_b, w_eh, w_he, w_ahe, w_aeh, w_fc);
    k_embed<<<(MM*EE + BB*2*HH + 255) / 256, 256>>>(target, src_emb, pos_emb);

    launch_tc(p_emb_h, p_emb_l, 0, EE, p_weh, b_eh, nullptr, 0, 1.f,
              p_xpad, p_xpad_h, p_xpad_l, 1, HH, MM, HH, EE);

    for (int l = 0; l < LL; l++) {
        const size_t wo = (size_t)l*2*HH*3*HH;
        // conv + fused GLU
        launch_tc(p_xpad_h, p_xpad_l, 2, HH, p_wt + wo,
                  p_cbias + (size_t)l*2*HH, nullptr, 0, 1.f,
                  p_conved, p_conved_h, p_conved_l, 0, HH, MM, 2*HH, 3*HH, 1);
        // comb = (conved @ w_ahe^T + b_ahe + embedded) * sqrt(.5)
        launch_tc(p_conved_h, p_conved_l, 0, HH, p_wahe,
                  b_ahe, p_emb, EE, SC, p_comb, nullptr, nullptr, 0, EE, MM, EE, HH);
        k_att<<<MM/32, 256>>>(encC, encComb);
        // conved = (att_enc @ w_aeh^T + b_aeh + conved)*SC; xpad = (conved + xpad)*SC
        launch_tc(p_attenc_h, p_attenc_l, 0, EE, p_waeh,
                  b_aeh, p_conved, HH, SC, p_conved, p_conved_h, p_conved_l,
                  0, HH, MM, HH, EE, 2, p_xpad, p_xpad_h, p_xpad_l);
    }

    launch_tc(p_xpad_h, p_xpad_l, 1, HH, p_whe, b_he, nullptr, 0, 1.f,
              p_comb, p_comb_h, p_comb_l, 0, EE, MM, EE, HH);
    launch_tc(p_comb_h, p_comb_l, 0, EE, p_wfc, b_fc, nullptr, 0, 1.f,
              out, nullptr, nullptr, 0, VV, MM, VV, EE);

    const long long ATT_OFF = (long long)MM * VV;
    if ((long long)out_size >= ATT_OFF + (long long)MM*SS) {
        k_attcopy<<<(MM*SS + 255) / 256, 256>>>(out + ATT_OFF);
    }
}